// round 3
// baseline (speedup 1.0000x reference)
#include <cuda_runtime.h>
#include <math.h>

// Problem constants
#define NB        8          // batch
#define CD        64         // embed dim
#define HH        4096       // spatial
#define NPTS      (NB*HH)    // 32768 points
#define NCODE     8192
#define ZQ_ELEMS  (NB*CD*HH) // 2097152

// Output layout (flat float32): [z_q | loss | indices | perplexity]
#define OUT_ZQ    0
#define OUT_LOSS  ZQ_ELEMS
#define OUT_IDX   (ZQ_ELEMS + 1)
#define OUT_PERP  (ZQ_ELEMS + 1 + NPTS)

// Scratch (static device allocations are allowed; heap/cudaMalloc are not)
__device__ float g_Et[CD * NCODE];     // transposed codebook [d][n], 2 MB
__device__ float g_enorm[NCODE];       // |e_n|^2 (fp32, squares rounded then summed)
__device__ int   g_idx[NPTS];          // argmax indices
__device__ int   g_hist[NCODE];        // code usage counts
__device__ float g_partial[2048];      // per-block SSD partials

// ---------------------------------------------------------------------------
// Prep: transpose E -> g_Et, compute |e|^2 (reference rounding: square each
// element to fp32, then sequential fp32 sum), zero histogram.
// ---------------------------------------------------------------------------
__global__ void vq_prep(const float* __restrict__ E) {
    int idx = blockIdx.x * 256 + threadIdx.x;
    if (idx < CD * NCODE) {
        int d = idx >> 13;         // / 8192
        int n = idx & (NCODE - 1);
        g_Et[idx] = E[n * CD + d];
    }
    if (idx < NCODE) {
        const float* r = E + idx * CD;
        float s = 0.f;
#pragma unroll
        for (int d = 0; d < CD; d++) s = __fadd_rn(s, __fmul_rn(r[d], r[d]));
        g_enorm[idx] = s;
        g_hist[idx] = 0;
    }
}

// ---------------------------------------------------------------------------
// Fused distance-GEMM + argmax with reference-exact fp32 rounding of
//   d = fl( fl(-|z|^2 - |e|^2) + 2*dot )
// and first-index tie-break.
// Block: 256 threads, tile = 128 points x 64 codes, K=64 fully resident.
// smem = 32KB (Zs) + 16KB (Es) = 48KB exactly (static limit).
// ---------------------------------------------------------------------------
__global__ void __launch_bounds__(256) vq_argmax(const float* __restrict__ z) {
    __shared__ float Zs[CD * 128];   // [k][m], 32 KB
    __shared__ float Es[CD * 64];    // [k][n], 16 KB

    const int tid = threadIdx.x;
    const int tx = tid & 15;         // code-column group (4 codes)
    const int ty = tid >> 4;         // point-row group (4+4 points)
    const int m0 = blockIdx.x * 128; // global point offset
    const float* zb = z + (m0 >> 12) * (CD * HH) + (m0 & (HH - 1));

    // Load Z tile: Zs[k][m] = z[b][k][h0+m]  (coalesced along m)
#pragma unroll
    for (int i = 0; i < 8; i++) {
        int q = tid + i * 256;           // 2048 float4 slots
        int k = q >> 5;
        int mc = (q & 31) << 2;
        *(float4*)(Zs + k * 128 + mc) = *(const float4*)(zb + k * HH + mc);
    }
    __syncthreads();

    // -|z|^2 per owned point row: square rounded to fp32, sequential fp32 sum
    float nzn[8];
#pragma unroll
    for (int i = 0; i < 8; i++) {
        int m = ((i >> 2) << 6) + ty * 4 + (i & 3);
        float s = 0.f;
#pragma unroll
        for (int k = 0; k < CD; k++) {
            float v = Zs[k * 128 + m];
            s = __fadd_rn(s, __fmul_rn(v, v));
        }
        nzn[i] = -s;
    }

    float best[8];
    int   bidx[8];
#pragma unroll
    for (int i = 0; i < 8; i++) { best[i] = -3.4e38f; bidx[i] = 0; }

    for (int n0 = 0; n0 < NCODE; n0 += 64) {
        __syncthreads();   // protect Es reuse from previous iteration readers
#pragma unroll
        for (int i = 0; i < 4; i++) {
            int q = tid + i * 256;       // 1024 float4 slots
            int k = q >> 4;
            int nc = (q & 15) << 2;
            *(float4*)(Es + k * 64 + nc) = *(const float4*)(g_Et + k * NCODE + n0 + nc);
        }
        __syncthreads();

        float acc[8][4];
#pragma unroll
        for (int i = 0; i < 8; i++)
#pragma unroll
            for (int j = 0; j < 4; j++) acc[i][j] = 0.f;

#pragma unroll 4
        for (int k = 0; k < CD; k++) {
            float a[8], bb[4];
            *(float4*)(a)     = *(float4*)(Zs + k * 128 + ty * 4);
            *(float4*)(a + 4) = *(float4*)(Zs + k * 128 + 64 + ty * 4);
            *(float4*)(bb)    = *(float4*)(Es + k * 64 + tx * 4);
#pragma unroll
            for (int i = 0; i < 8; i++)
#pragma unroll
                for (int j = 0; j < 4; j++) acc[i][j] += a[i] * bb[j];
        }

        float4 en4 = *(const float4*)(g_enorm + n0 + tx * 4);
        float en[4] = {en4.x, en4.y, en4.z, en4.w};
#pragma unroll
        for (int i = 0; i < 8; i++)
#pragma unroll
            for (int j = 0; j < 4; j++) {
                // reference rounding chain: fl(fl(-zn - en) + 2*dot)
                float base = __fadd_rn(nzn[i], -en[j]);
                float v = __fadd_rn(base, 2.0f * acc[i][j]);
                // in-thread candidates arrive in ascending index order,
                // so strict > keeps the first (lowest-index) max
                if (v > best[i]) { best[i] = v; bidx[i] = n0 + tx * 4 + j; }
            }
    }

    // Reduce across the 16 threads (tx) sharing each point row.
    __syncthreads();
    float* sval = Zs;                       // 128*16 floats
    int*   sidx = (int*)(Zs + 128 * 16);    // 128*16 ints
#pragma unroll
    for (int i = 0; i < 8; i++) {
        int m = ((i >> 2) << 6) + ty * 4 + (i & 3);
        sval[m * 16 + tx] = best[i];
        sidx[m * 16 + tx] = bidx[i];
    }
    __syncthreads();
    if (tid < 128) {
        float bv = -3.4e38f; int bi = 0x7fffffff;
        for (int t = 0; t < 16; t++) {
            float v = sval[tid * 16 + t];
            int   ix = sidx[tid * 16 + t];
            // first-index tie-break across threads (indices interleave by tx)
            if (v > bv || (v == bv && ix < bi)) { bv = v; bi = ix; }
        }
        g_idx[m0 + tid] = bi;
    }
}

// ---------------------------------------------------------------------------
// Gather z_q into out, accumulate per-block SSD partial.
// ---------------------------------------------------------------------------
__global__ void vq_gather(const float* __restrict__ z, const float* __restrict__ E,
                          float* __restrict__ out) {
    __shared__ float red[256];
    int tid = threadIdx.x;
    int base = (blockIdx.x * 256 + tid) * 4;    // linear offset in (B,C,H)
    int h = base & (HH - 1);
    int c = (base >> 12) & (CD - 1);
    int b = base >> 18;
    const int* gi = g_idx + b * HH + h;
    float4 zv = *(const float4*)(z + base);
    float e0 = E[gi[0] * CD + c];
    float e1 = E[gi[1] * CD + c];
    float e2 = E[gi[2] * CD + c];
    float e3 = E[gi[3] * CD + c];
    *(float4*)(out + OUT_ZQ + base) = make_float4(e0, e1, e2, e3);
    float d0 = e0 - zv.x, d1 = e1 - zv.y, d2 = e2 - zv.z, d3 = e3 - zv.w;
    red[tid] = d0 * d0 + d1 * d1 + d2 * d2 + d3 * d3;
    __syncthreads();
    for (int off = 128; off > 0; off >>= 1) {
        if (tid < off) red[tid] += red[tid + off];
        __syncthreads();
    }
    if (tid == 0) g_partial[blockIdx.x] = red[0];
}

// ---------------------------------------------------------------------------
// Histogram + write indices as float.
// ---------------------------------------------------------------------------
__global__ void vq_hist(float* __restrict__ out) {
    int n = blockIdx.x * 256 + threadIdx.x;
    int idx = g_idx[n];
    atomicAdd(&g_hist[idx], 1);
    out[OUT_IDX + n] = (float)idx;
}

// ---------------------------------------------------------------------------
// Final deterministic reductions: loss + perplexity.
// ---------------------------------------------------------------------------
__global__ void vq_final(float* __restrict__ out) {
    __shared__ float red[256];
    int tid = threadIdx.x;

    float s = 0.f;
    for (int i = tid; i < 2048; i += 256) s += g_partial[i];
    red[tid] = s;
    __syncthreads();
    for (int off = 128; off > 0; off >>= 1) {
        if (tid < off) red[tid] += red[tid + off];
        __syncthreads();
    }
    if (tid == 0)
        out[OUT_LOSS] = 1.25f * red[0] / (float)ZQ_ELEMS;  // (1 + BETA) * mean
    __syncthreads();

    float ent = 0.f;
    for (int i = tid; i < NCODE; i += 256) {
        float p = (float)g_hist[i] * (1.f / (float)NPTS);
        ent += p * logf(p + 1e-10f);
    }
    red[tid] = ent;
    __syncthreads();
    for (int off = 128; off > 0; off >>= 1) {
        if (tid < off) red[tid] += red[tid + off];
        __syncthreads();
    }
    if (tid == 0) out[OUT_PERP] = expf(-red[0]);
}

// ---------------------------------------------------------------------------
extern "C" void kernel_launch(void* const* d_in, const int* in_sizes, int n_in,
                              void* d_out, int out_size) {
    const float* z = (const float*)d_in[0];        // (8, 64, 4096) f32
    const float* E = (const float*)d_in[1];        // (8192, 64) f32
    float* out = (float*)d_out;

    vq_prep  <<<2048, 256>>>(E);
    vq_argmax<<<NPTS / 128, 256>>>(z);
    vq_gather<<<2048, 256>>>(z, E, out);
    vq_hist  <<<NPTS / 256, 256>>>(out);
    vq_final <<<1, 256>>>(out);
}

// round 4
// speedup vs baseline: 1.7052x; 1.7052x over previous
#include <cuda_runtime.h>
#include <math.h>
#include <stdint.h>

// Problem constants
#define NB        8
#define CD        64
#define HH        4096
#define NPTS      (NB*HH)    // 32768
#define NCODE     8192
#define ZQ_ELEMS  (NB*CD*HH) // 2097152

// Output layout (flat float32): [z_q | loss | indices | perplexity]
#define OUT_ZQ    0
#define OUT_LOSS  ZQ_ELEMS
#define OUT_IDX   (ZQ_ELEMS + 1)
#define OUT_PERP  (ZQ_ELEMS + 1 + NPTS)

// B fragments: [nf(1024)][kc(8)][lane(32)] float4 = (b0hi, b1hi, b0lo, b1lo)
// for mma.m16n8k8 tf32: b0 = B[k = kc*8 + lane%4][n = nf*8 + lane/4], b1 = k+4.
// B[k][n] = 2*E[n][k] split into tf32 hi+lo.
__device__ float4 g_Bfrag[1024 * 8 * 32];   // 4 MB
__device__ float  g_enorm[NCODE];
__device__ int    g_idx[NPTS];
__device__ int    g_hist[NCODE];
__device__ float  g_partial[2048];

// ---------------------------------------------------------------------------
__device__ __forceinline__ float tf32_rna(float x) {
    uint32_t u;
    asm("cvt.rna.tf32.f32 %0, %1;" : "=r"(u) : "f"(x));
    return __uint_as_float(u);
}

__device__ __forceinline__ void mma_tf32(float& d0, float& d1, float& d2, float& d3,
                                         uint32_t a0, uint32_t a1, uint32_t a2, uint32_t a3,
                                         uint32_t b0, uint32_t b1) {
    asm volatile(
        "mma.sync.aligned.m16n8k8.row.col.f32.tf32.tf32.f32 "
        "{%0,%1,%2,%3},{%4,%5,%6,%7},{%8,%9},{%0,%1,%2,%3};"
        : "+f"(d0), "+f"(d1), "+f"(d2), "+f"(d3)
        : "r"(a0), "r"(a1), "r"(a2), "r"(a3), "r"(b0), "r"(b1));
}

__device__ __forceinline__ void cp_async16(uint32_t saddr, const void* gptr) {
    asm volatile("cp.async.cg.shared.global [%0], [%1], 16;" :: "r"(saddr), "l"(gptr));
}

// ---------------------------------------------------------------------------
// Prep A: |e|^2 (reference rounding chain) + zero histogram
// ---------------------------------------------------------------------------
__global__ void vq_prep(const float* __restrict__ E) {
    int idx = blockIdx.x * 256 + threadIdx.x;
    if (idx < NCODE) {
        const float* r = E + idx * CD;
        float s = 0.f;
#pragma unroll
        for (int d = 0; d < CD; d++) s = __fadd_rn(s, __fmul_rn(r[d], r[d]));
        g_enorm[idx] = s;
        g_hist[idx] = 0;
    }
}

// ---------------------------------------------------------------------------
// Prep B: pack codebook into mma fragment-lane order, tf32 hi/lo split of 2E.
// grid 1024 x 256 -> 262144 threads, one float4 each.
// ---------------------------------------------------------------------------
__global__ void vq_prep_bfrag(const float* __restrict__ E) {
    int idx = blockIdx.x * 256 + threadIdx.x;       // [nf*8+kc]*32 + lane
    int lane = idx & 31;
    int kc = (idx >> 5) & 7;
    int nf = idx >> 8;
    int n = nf * 8 + (lane >> 2);
    int k0 = kc * 8 + (lane & 3);
    float e0 = 2.0f * E[n * CD + k0];
    float e1 = 2.0f * E[n * CD + k0 + 4];
    float h0 = tf32_rna(e0), h1 = tf32_rna(e1);
    float l0 = tf32_rna(e0 - h0), l1 = tf32_rna(e1 - h1);
    g_Bfrag[idx] = make_float4(h0, h1, l0, l1);
}

// ---------------------------------------------------------------------------
// Fused 3xTF32 distance-GEMM + argmax.
// CTA: 256 threads = 8 warps; warp w owns rows [blk*256 + w*32, +32).
// Warp tile m32 x n32, K=64 resident in registers (A hi+lo).
// grid 128.
// ---------------------------------------------------------------------------
__global__ void __launch_bounds__(256, 1) vq_argmax(const float* __restrict__ z) {
    __shared__ float4 Bs[2][1024];     // 32 KB double buffer (one n-tile of 32 codes)

    const int tid = threadIdx.x;
    const int lane = tid & 31;
    const int w = tid >> 5;
    const int blk = blockIdx.x;
    const int b = (blk * 256) >> 12;
    const int hb = (blk * 256) & (HH - 1);
    const float* zb = z + b * (CD * HH);
    const int hw = hb + w * 32;                 // this warp's h base

    // ---- -|z|^2 per row (reference sequential chain); lane l -> row hw+l
    float s = 0.f;
    {
        int h = hw + lane;
#pragma unroll
        for (int k = 0; k < CD; k++) {
            float v = zb[k * HH + h];
            s = __fadd_rn(s, __fmul_rn(v, v));
        }
    }
    float nznl = -s;
    // nzn[mf][rr]: row (warp-local) = mf*16 + (lane>>2) + rr*8
    float nzn[2][2];
#pragma unroll
    for (int mf = 0; mf < 2; mf++) {
        nzn[mf][0] = __shfl_sync(0xffffffffu, nznl, mf * 16 + (lane >> 2));
        nzn[mf][1] = __shfl_sync(0xffffffffu, nznl, mf * 16 + (lane >> 2) + 8);
    }

    // ---- load A fragments (hi/lo tf32), resident for whole N sweep
    uint32_t Ahi[2][8][4], Alo[2][8][4];
#pragma unroll
    for (int mf = 0; mf < 2; mf++) {
        int r0 = mf * 16 + (lane >> 2);
        int h0 = hw + r0, h1 = hw + r0 + 8;
#pragma unroll
        for (int kc = 0; kc < 8; kc++) {
            int k0 = kc * 8 + (lane & 3);
            float f0 = zb[k0 * HH + h0];
            float f1 = zb[k0 * HH + h1];
            float f2 = zb[(k0 + 4) * HH + h0];
            float f3 = zb[(k0 + 4) * HH + h1];
            float hi;
            hi = tf32_rna(f0); Ahi[mf][kc][0] = __float_as_uint(hi); Alo[mf][kc][0] = __float_as_uint(tf32_rna(f0 - hi));
            hi = tf32_rna(f1); Ahi[mf][kc][1] = __float_as_uint(hi); Alo[mf][kc][1] = __float_as_uint(tf32_rna(f1 - hi));
            hi = tf32_rna(f2); Ahi[mf][kc][2] = __float_as_uint(hi); Alo[mf][kc][2] = __float_as_uint(tf32_rna(f2 - hi));
            hi = tf32_rna(f3); Ahi[mf][kc][3] = __float_as_uint(hi); Alo[mf][kc][3] = __float_as_uint(tf32_rna(f3 - hi));
        }
    }

    float best[2][2];
    int   bidx[2][2];
#pragma unroll
    for (int mf = 0; mf < 2; mf++)
#pragma unroll
        for (int rr = 0; rr < 2; rr++) { best[mf][rr] = -3.4e38f; bidx[mf][rr] = 0; }

    const int NT = NCODE / 32;   // 256 n-tiles

    // prologue: stage tile 0 into buf 0
    {
#pragma unroll
        for (int i = 0; i < 4; i++) {
            int q = tid + i * 256;
            uint32_t sa = (uint32_t)__cvta_generic_to_shared(&Bs[0][q]);
            cp_async16(sa, &g_Bfrag[q]);
        }
        asm volatile("cp.async.commit_group;" ::: "memory");
    }

#pragma unroll 1
    for (int t = 0; t < NT; t++) {
        const int cur = t & 1;
        if (t + 1 < NT) {
            const int nxt = cur ^ 1;
#pragma unroll
            for (int i = 0; i < 4; i++) {
                int q = tid + i * 256;
                uint32_t sa = (uint32_t)__cvta_generic_to_shared(&Bs[nxt][q]);
                cp_async16(sa, &g_Bfrag[(t + 1) * 1024 + q]);
            }
            asm volatile("cp.async.commit_group;" ::: "memory");
            asm volatile("cp.async.wait_group 1;" ::: "memory");
        } else {
            asm volatile("cp.async.wait_group 0;" ::: "memory");
        }
        __syncthreads();   // tile t visible to all warps

        float D[2][4][4];
#pragma unroll
        for (int mf = 0; mf < 2; mf++)
#pragma unroll
            for (int nf = 0; nf < 4; nf++)
#pragma unroll
                for (int c = 0; c < 4; c++) D[mf][nf][c] = 0.f;

#pragma unroll
        for (int kc = 0; kc < 8; kc++) {
            float4 bq[4];
#pragma unroll
            for (int nf = 0; nf < 4; nf++)
                bq[nf] = Bs[cur][(nf * 8 + kc) * 32 + lane];
#pragma unroll
            for (int mf = 0; mf < 2; mf++)
#pragma unroll
                for (int nf = 0; nf < 4; nf++) {
                    uint32_t b0h = __float_as_uint(bq[nf].x);
                    uint32_t b1h = __float_as_uint(bq[nf].y);
                    uint32_t b0l = __float_as_uint(bq[nf].z);
                    uint32_t b1l = __float_as_uint(bq[nf].w);
                    mma_tf32(D[mf][nf][0], D[mf][nf][1], D[mf][nf][2], D[mf][nf][3],
                             Ahi[mf][kc][0], Ahi[mf][kc][1], Ahi[mf][kc][2], Ahi[mf][kc][3],
                             b0h, b1h);
                    mma_tf32(D[mf][nf][0], D[mf][nf][1], D[mf][nf][2], D[mf][nf][3],
                             Ahi[mf][kc][0], Ahi[mf][kc][1], Ahi[mf][kc][2], Ahi[mf][kc][3],
                             b0l, b1l);
                    mma_tf32(D[mf][nf][0], D[mf][nf][1], D[mf][nf][2], D[mf][nf][3],
                             Alo[mf][kc][0], Alo[mf][kc][1], Alo[mf][kc][2], Alo[mf][kc][3],
                             b0h, b1h);
                }
        }
        __syncthreads();   // all warps done reading buf `cur` before t+1 overwrites it

        // epilogue: v = fl(fl(-zn - en) + D), strict-> first-index argmax
        const int nbase = t * 32;
#pragma unroll
        for (int nf = 0; nf < 4; nf++) {
            const int ncol = nbase + nf * 8 + (lane & 3) * 2;
            float2 en2 = *(const float2*)(g_enorm + ncol);
#pragma unroll
            for (int mf = 0; mf < 2; mf++) {
                float v0 = __fadd_rn(__fadd_rn(nzn[mf][0], -en2.x), D[mf][nf][0]);
                if (v0 > best[mf][0]) { best[mf][0] = v0; bidx[mf][0] = ncol; }
                float v1 = __fadd_rn(__fadd_rn(nzn[mf][0], -en2.y), D[mf][nf][1]);
                if (v1 > best[mf][0]) { best[mf][0] = v1; bidx[mf][0] = ncol + 1; }
                float v2 = __fadd_rn(__fadd_rn(nzn[mf][1], -en2.x), D[mf][nf][2]);
                if (v2 > best[mf][1]) { best[mf][1] = v2; bidx[mf][1] = ncol; }
                float v3 = __fadd_rn(__fadd_rn(nzn[mf][1], -en2.y), D[mf][nf][3]);
                if (v3 > best[mf][1]) { best[mf][1] = v3; bidx[mf][1] = ncol + 1; }
            }
        }
    }

    // quad reduce (lanes sharing a row differ in lane%4), first-index tie-break
    const int Wrow = blk * 256 + w * 32;
#pragma unroll
    for (int mf = 0; mf < 2; mf++)
#pragma unroll
        for (int rr = 0; rr < 2; rr++) {
            float v = best[mf][rr];
            int ix = bidx[mf][rr];
#pragma unroll
            for (int off = 1; off <= 2; off <<= 1) {
                float ov = __shfl_xor_sync(0xffffffffu, v, off);
                int   oi = __shfl_xor_sync(0xffffffffu, ix, off);
                if (ov > v || (ov == v && oi < ix)) { v = ov; ix = oi; }
            }
            if ((lane & 3) == 0)
                g_idx[Wrow + mf * 16 + (lane >> 2) + rr * 8] = ix;
        }
}

// ---------------------------------------------------------------------------
// Gather z_q into out, accumulate per-block SSD partial.
// ---------------------------------------------------------------------------
__global__ void vq_gather(const float* __restrict__ z, const float* __restrict__ E,
                          float* __restrict__ out) {
    __shared__ float red[256];
    int tid = threadIdx.x;
    int base = (blockIdx.x * 256 + tid) * 4;
    int h = base & (HH - 1);
    int c = (base >> 12) & (CD - 1);
    int b = base >> 18;
    const int* gi = g_idx + b * HH + h;
    float4 zv = *(const float4*)(z + base);
    float e0 = E[gi[0] * CD + c];
    float e1 = E[gi[1] * CD + c];
    float e2 = E[gi[2] * CD + c];
    float e3 = E[gi[3] * CD + c];
    *(float4*)(out + OUT_ZQ + base) = make_float4(e0, e1, e2, e3);
    float d0 = e0 - zv.x, d1 = e1 - zv.y, d2 = e2 - zv.z, d3 = e3 - zv.w;
    red[tid] = d0 * d0 + d1 * d1 + d2 * d2 + d3 * d3;
    __syncthreads();
    for (int off = 128; off > 0; off >>= 1) {
        if (tid < off) red[tid] += red[tid + off];
        __syncthreads();
    }
    if (tid == 0) g_partial[blockIdx.x] = red[0];
}

// ---------------------------------------------------------------------------
__global__ void vq_hist(float* __restrict__ out) {
    int n = blockIdx.x * 256 + threadIdx.x;
    int idx = g_idx[n];
    atomicAdd(&g_hist[idx], 1);
    out[OUT_IDX + n] = (float)idx;
}

// ---------------------------------------------------------------------------
__global__ void vq_final(float* __restrict__ out) {
    __shared__ float red[256];
    int tid = threadIdx.x;

    float s = 0.f;
    for (int i = tid; i < 2048; i += 256) s += g_partial[i];
    red[tid] = s;
    __syncthreads();
    for (int off = 128; off > 0; off >>= 1) {
        if (tid < off) red[tid] += red[tid + off];
        __syncthreads();
    }
    if (tid == 0)
        out[OUT_LOSS] = 1.25f * red[0] / (float)ZQ_ELEMS;
    __syncthreads();

    float ent = 0.f;
    for (int i = tid; i < NCODE; i += 256) {
        float p = (float)g_hist[i] * (1.f / (float)NPTS);
        ent += p * logf(p + 1e-10f);
    }
    red[tid] = ent;
    __syncthreads();
    for (int off = 128; off > 0; off >>= 1) {
        if (tid < off) red[tid] += red[tid + off];
        __syncthreads();
    }
    if (tid == 0) out[OUT_PERP] = expf(-red[0]);
}

// ---------------------------------------------------------------------------
extern "C" void kernel_launch(void* const* d_in, const int* in_sizes, int n_in,
                              void* d_out, int out_size) {
    const float* z = (const float*)d_in[0];        // (8, 64, 4096) f32
    const float* E = (const float*)d_in[1];        // (8192, 64) f32
    float* out = (float*)d_out;

    vq_prep      <<<32, 256>>>(E);
    vq_prep_bfrag<<<1024, 256>>>(E);
    vq_argmax    <<<128, 256>>>(z);
    vq_gather    <<<2048, 256>>>(z, E, out);
    vq_hist      <<<NPTS / 256, 256>>>(out);
    vq_final     <<<1, 256>>>(out);
}

// round 6
// speedup vs baseline: 2.5269x; 1.4819x over previous
#include <cuda_runtime.h>
#include <cuda_fp16.h>
#include <math.h>
#include <stdint.h>

// Problem constants
#define NB        8
#define CD        64
#define HH        4096
#define NPTS      (NB*HH)    // 32768
#define NCODE     8192
#define ZQ_ELEMS  (NB*CD*HH) // 2097152

// Output layout (flat float32): [z_q | loss | indices | perplexity]
#define OUT_ZQ    0
#define OUT_LOSS  ZQ_ELEMS
#define OUT_IDX   (ZQ_ELEMS + 1)
#define OUT_PERP  (ZQ_ELEMS + 1 + NPTS)

#define LO_SCALE   4096.0f
#define LO_INV     2.44140625e-4f   // 1/4096

// B fragments for mma.m16n8k16.f16: [nf(1024)][kc(4)][lane(32)] uint4 =
// (b0_hi, b1_hi, b0_lo, b1_lo); b0 = half2{B[k0][c],B[k0+1][c]}, b1 = k0+8 pair,
// c = nf*8 + lane/4, k0 = kc*16 + (lane%4)*2.  B[k][n] = 2*E[n][k], hi/lo fp16
// split with lo scaled by 4096.
__device__ uint4  g_Bfrag[1024 * 4 * 32];   // 2 MB
__device__ float  g_enorm[NCODE];
__device__ int    g_idx[NPTS];
__device__ int    g_hist[NCODE];
__device__ float  g_partial[2048];

// ---------------------------------------------------------------------------
__device__ __forceinline__ uint32_t pack_h2(__half a, __half b) {
    __half2 h = __halves2half2(a, b);
    return *(uint32_t*)&h;
}

__device__ __forceinline__ void split16(float f, __half& hi, __half& lo) {
    hi = __float2half_rn(f);
    lo = __float2half_rn((f - __half2float(hi)) * LO_SCALE);
}

__device__ __forceinline__ void mma_f16(float& d0, float& d1, float& d2, float& d3,
                                        uint32_t a0, uint32_t a1, uint32_t a2, uint32_t a3,
                                        uint32_t b0, uint32_t b1) {
    asm volatile(
        "mma.sync.aligned.m16n8k16.row.col.f32.f16.f16.f32 "
        "{%0,%1,%2,%3},{%4,%5,%6,%7},{%8,%9},{%0,%1,%2,%3};"
        : "+f"(d0), "+f"(d1), "+f"(d2), "+f"(d3)
        : "r"(a0), "r"(a1), "r"(a2), "r"(a3), "r"(b0), "r"(b1));
}

__device__ __forceinline__ void cp_async16(uint32_t saddr, const void* gptr) {
    asm volatile("cp.async.cg.shared.global [%0], [%1], 16;" :: "r"(saddr), "l"(gptr));
}

// ---------------------------------------------------------------------------
// Prep A: |e|^2 (reference rounding chain) + zero histogram
// ---------------------------------------------------------------------------
__global__ void vq_prep(const float* __restrict__ E) {
    int idx = blockIdx.x * 256 + threadIdx.x;
    if (idx < NCODE) {
        const float* r = E + idx * CD;
        float s = 0.f;
#pragma unroll
        for (int d = 0; d < CD; d++) s = __fadd_rn(s, __fmul_rn(r[d], r[d]));
        g_enorm[idx] = s;
        g_hist[idx] = 0;
    }
}

// ---------------------------------------------------------------------------
// Prep B: pack codebook into m16n8k16 fragment-lane order, fp16 hi/lo of 2E.
// grid 512 x 256 -> 131072 threads, one uint4 each.
// ---------------------------------------------------------------------------
__global__ void vq_prep_bfrag(const float* __restrict__ E) {
    int idx = blockIdx.x * 256 + threadIdx.x;     // [nf*4+kc]*32 + lane
    int lane = idx & 31;
    int kc = (idx >> 5) & 3;
    int nf = idx >> 7;
    int n = nf * 8 + (lane >> 2);
    int k0 = kc * 16 + (lane & 3) * 2;
    const float* r = E + n * CD;
    float f0 = 2.0f * r[k0];
    float f1 = 2.0f * r[k0 + 1];
    float f2 = 2.0f * r[k0 + 8];
    float f3 = 2.0f * r[k0 + 9];
    __half h0, l0, h1, l1, h2, l2, h3, l3;
    split16(f0, h0, l0); split16(f1, h1, l1);
    split16(f2, h2, l2); split16(f3, h3, l3);
    uint4 v;
    v.x = pack_h2(h0, h1);   // b0 hi
    v.y = pack_h2(h2, h3);   // b1 hi
    v.z = pack_h2(l0, l1);   // b0 lo
    v.w = pack_h2(l2, l3);   // b1 lo
    g_Bfrag[idx] = v;
}

// ---------------------------------------------------------------------------
// Fused split-fp16 distance-GEMM + argmax.
// CTA: 256 threads = 8 warps; warp w owns rows [blk*256 + w*32, +32).
// Warp tile m32 x n32, K=64 resident in registers (A hi+lo fp16 pairs).
// dot = Dh + Dx/4096;  v = fl(fl(-zn - en) + dot); first-index argmax.
// grid 128.
// ---------------------------------------------------------------------------
__global__ void __launch_bounds__(256, 1) vq_argmax(const float* __restrict__ z) {
    __shared__ uint4 Bs[2][512];     // 16 KB double buffer (n-tile of 32 codes)

    const int tid = threadIdx.x;
    const int lane = tid & 31;
    const int w = tid >> 5;
    const int blk = blockIdx.x;
    const int b = (blk * 256) >> 12;
    const int hb = (blk * 256) & (HH - 1);
    const float* zb = z + b * (CD * HH);
    const int hw = hb + w * 32;

    // ---- -|z|^2 per row (reference sequential chain); lane l -> row hw+l
    float s = 0.f;
    {
        int h = hw + lane;
#pragma unroll
        for (int k = 0; k < CD; k++) {
            float v = zb[k * HH + h];
            s = __fadd_rn(s, __fmul_rn(v, v));
        }
    }
    float nznl = -s;
    float nzn[2][2];
#pragma unroll
    for (int mf = 0; mf < 2; mf++) {
        nzn[mf][0] = __shfl_sync(0xffffffffu, nznl, mf * 16 + (lane >> 2));
        nzn[mf][1] = __shfl_sync(0xffffffffu, nznl, mf * 16 + (lane >> 2) + 8);
    }

    // ---- A fragments (hi/lo fp16), resident for whole N sweep.
    // a0:{r,k0,k0+1} a1:{r+8,..} a2:{r,k0+8,k0+9} a3:{r+8,k0+8,k0+9}
    uint32_t Ahi[2][4][4], Alo[2][4][4];
#pragma unroll
    for (int mf = 0; mf < 2; mf++) {
        int r0 = hw + mf * 16 + (lane >> 2);
        int r1 = r0 + 8;
#pragma unroll
        for (int kc = 0; kc < 4; kc++) {
            int k0 = kc * 16 + (lane & 3) * 2;
#pragma unroll
            for (int q = 0; q < 4; q++) {
                int rr = (q & 1) ? r1 : r0;
                int kk = k0 + ((q & 2) ? 8 : 0);
                float fA = zb[kk * HH + rr];
                float fB = zb[(kk + 1) * HH + rr];
                __half hA, lA, hB, lB;
                split16(fA, hA, lA);
                split16(fB, hB, lB);
                Ahi[mf][kc][q] = pack_h2(hA, hB);
                Alo[mf][kc][q] = pack_h2(lA, lB);
            }
        }
    }

    float best[2][2];
    int   bidx[2][2];
#pragma unroll
    for (int mf = 0; mf < 2; mf++)
#pragma unroll
        for (int rr = 0; rr < 2; rr++) { best[mf][rr] = -3.4e38f; bidx[mf][rr] = 0; }

    const int NT = NCODE / 32;   // 256 n-tiles

    // prologue: stage tile 0 into buf 0 (512 uint4, 2 per thread)
    {
#pragma unroll
        for (int i = 0; i < 2; i++) {
            int q = tid + i * 256;
            uint32_t sa = (uint32_t)__cvta_generic_to_shared(&Bs[0][q]);
            cp_async16(sa, &g_Bfrag[q]);
        }
        asm volatile("cp.async.commit_group;" ::: "memory");
    }

#pragma unroll 1
    for (int t = 0; t < NT; t++) {
        const int cur = t & 1;
        if (t + 1 < NT) {
            const int nxt = cur ^ 1;
#pragma unroll
            for (int i = 0; i < 2; i++) {
                int q = tid + i * 256;
                uint32_t sa = (uint32_t)__cvta_generic_to_shared(&Bs[nxt][q]);
                cp_async16(sa, &g_Bfrag[(t + 1) * 512 + q]);
            }
            asm volatile("cp.async.commit_group;" ::: "memory");
            asm volatile("cp.async.wait_group 1;" ::: "memory");
        } else {
            asm volatile("cp.async.wait_group 0;" ::: "memory");
        }
        __syncthreads();   // tile t visible

        float Dh[2][4][4], Dx[2][4][4];
#pragma unroll
        for (int mf = 0; mf < 2; mf++)
#pragma unroll
            for (int nf = 0; nf < 4; nf++)
#pragma unroll
                for (int c = 0; c < 4; c++) { Dh[mf][nf][c] = 0.f; Dx[mf][nf][c] = 0.f; }

#pragma unroll
        for (int kc = 0; kc < 4; kc++) {
            uint4 bq[4];
#pragma unroll
            for (int nf = 0; nf < 4; nf++)
                bq[nf] = Bs[cur][(nf * 4 + kc) * 32 + lane];
#pragma unroll
            for (int mf = 0; mf < 2; mf++)
#pragma unroll
                for (int nf = 0; nf < 4; nf++) {
                    // hi*hi -> Dh
                    mma_f16(Dh[mf][nf][0], Dh[mf][nf][1], Dh[mf][nf][2], Dh[mf][nf][3],
                            Ahi[mf][kc][0], Ahi[mf][kc][1], Ahi[mf][kc][2], Ahi[mf][kc][3],
                            bq[nf].x, bq[nf].y);
                    // hi*lo + lo*hi -> Dx (scale 4096)
                    mma_f16(Dx[mf][nf][0], Dx[mf][nf][1], Dx[mf][nf][2], Dx[mf][nf][3],
                            Ahi[mf][kc][0], Ahi[mf][kc][1], Ahi[mf][kc][2], Ahi[mf][kc][3],
                            bq[nf].z, bq[nf].w);
                    mma_f16(Dx[mf][nf][0], Dx[mf][nf][1], Dx[mf][nf][2], Dx[mf][nf][3],
                            Alo[mf][kc][0], Alo[mf][kc][1], Alo[mf][kc][2], Alo[mf][kc][3],
                            bq[nf].x, bq[nf].y);
                }
        }
        __syncthreads();   // all reads of buf `cur` done before t+1 overwrites

        // epilogue: dot = Dh + Dx/4096; v = fl(fl(-zn - en) + dot)
        const int nbase = t * 32;
#pragma unroll
        for (int nf = 0; nf < 4; nf++) {
            const int ncol = nbase + nf * 8 + (lane & 3) * 2;
            float2 en2 = *(const float2*)(g_enorm + ncol);
#pragma unroll
            for (int mf = 0; mf < 2; mf++) {
                float dot0 = __fmaf_rn(Dx[mf][nf][0], LO_INV, Dh[mf][nf][0]);
                float dot1 = __fmaf_rn(Dx[mf][nf][1], LO_INV, Dh[mf][nf][1]);
                float dot2 = __fmaf_rn(Dx[mf][nf][2], LO_INV, Dh[mf][nf][2]);
                float dot3 = __fmaf_rn(Dx[mf][nf][3], LO_INV, Dh[mf][nf][3]);
                float v0 = __fadd_rn(__fadd_rn(nzn[mf][0], -en2.x), dot0);
                if (v0 > best[mf][0]) { best[mf][0] = v0; bidx[mf][0] = ncol; }
                float v1 = __fadd_rn(__fadd_rn(nzn[mf][0], -en2.y), dot1);
                if (v1 > best[mf][0]) { best[mf][0] = v1; bidx[mf][0] = ncol + 1; }
                float v2 = __fadd_rn(__fadd_rn(nzn[mf][1], -en2.x), dot2);
                if (v2 > best[mf][1]) { best[mf][1] = v2; bidx[mf][1] = ncol; }
                float v3 = __fadd_rn(__fadd_rn(nzn[mf][1], -en2.y), dot3);
                if (v3 > best[mf][1]) { best[mf][1] = v3; bidx[mf][1] = ncol + 1; }
            }
        }
    }

    // quad reduce (lanes sharing a row differ in lane%4), first-index tie-break
    const int Wrow = blk * 256 + w * 32;
#pragma unroll
    for (int mf = 0; mf < 2; mf++)
#pragma unroll
        for (int rr = 0; rr < 2; rr++) {
            float v = best[mf][rr];
            int ix = bidx[mf][rr];
#pragma unroll
            for (int off = 1; off <= 2; off <<= 1) {
                float ov = __shfl_xor_sync(0xffffffffu, v, off);
                int   oi = __shfl_xor_sync(0xffffffffu, ix, off);
                if (ov > v || (ov == v && oi < ix)) { v = ov; ix = oi; }
            }
            if ((lane & 3) == 0)
                g_idx[Wrow + mf * 16 + (lane >> 2) + rr * 8] = ix;
        }
}

// ---------------------------------------------------------------------------
// Gather z_q into out, accumulate per-block SSD partial.
// ---------------------------------------------------------------------------
__global__ void vq_gather(const float* __restrict__ z, const float* __restrict__ E,
                          float* __restrict__ out) {
    __shared__ float red[256];
    int tid = threadIdx.x;
    int base = (blockIdx.x * 256 + tid) * 4;
    int h = base & (HH - 1);
    int c = (base >> 12) & (CD - 1);
    int b = base >> 18;
    const int* gi = g_idx + b * HH + h;
    float4 zv = *(const float4*)(z + base);
    float e0 = E[gi[0] * CD + c];
    float e1 = E[gi[1] * CD + c];
    float e2 = E[gi[2] * CD + c];
    float e3 = E[gi[3] * CD + c];
    *(float4*)(out + OUT_ZQ + base) = make_float4(e0, e1, e2, e3);
    float d0 = e0 - zv.x, d1 = e1 - zv.y, d2 = e2 - zv.z, d3 = e3 - zv.w;
    red[tid] = d0 * d0 + d1 * d1 + d2 * d2 + d3 * d3;
    __syncthreads();
    for (int off = 128; off > 0; off >>= 1) {
        if (tid < off) red[tid] += red[tid + off];
        __syncthreads();
    }
    if (tid == 0) g_partial[blockIdx.x] = red[0];
}

// ---------------------------------------------------------------------------
__global__ void vq_hist(float* __restrict__ out) {
    int n = blockIdx.x * 256 + threadIdx.x;
    int idx = g_idx[n];
    atomicAdd(&g_hist[idx], 1);
    out[OUT_IDX + n] = (float)idx;
}

// ---------------------------------------------------------------------------
__global__ void vq_final(float* __restrict__ out) {
    __shared__ float red[256];
    int tid = threadIdx.x;

    float s = 0.f;
    for (int i = tid; i < 2048; i += 256) s += g_partial[i];
    red[tid] = s;
    __syncthreads();
    for (int off = 128; off > 0; off >>= 1) {
        if (tid < off) red[tid] += red[tid + off];
        __syncthreads();
    }
    if (tid == 0)
        out[OUT_LOSS] = 1.25f * red[0] / (float)ZQ_ELEMS;
    __syncthreads();

    float ent = 0.f;
    for (int i = tid; i < NCODE; i += 256) {
        float p = (float)g_hist[i] * (1.f / (float)NPTS);
        ent += p * logf(p + 1e-10f);
    }
    red[tid] = ent;
    __syncthreads();
    for (int off = 128; off > 0; off >>= 1) {
        if (tid < off) red[tid] += red[tid + off];
        __syncthreads();
    }
    if (tid == 0) out[OUT_PERP] = expf(-red[0]);
}

// ---------------------------------------------------------------------------
extern "C" void kernel_launch(void* const* d_in, const int* in_sizes, int n_in,
                              void* d_out, int out_size) {
    const float* z = (const float*)d_in[0];        // (8, 64, 4096) f32
    const float* E = (const float*)d_in[1];        // (8192, 64) f32
    float* out = (float*)d_out;

    vq_prep      <<<32, 256>>>(E);
    vq_prep_bfrag<<<512, 256>>>(E);
    vq_argmax    <<<128, 256>>>(z);
    vq_gather    <<<2048, 256>>>(z, E, out);
    vq_hist      <<<NPTS / 256, 256>>>(out);
    vq_final     <<<1, 256>>>(out);
}

// round 7
// speedup vs baseline: 2.5376x; 1.0043x over previous
#include <cuda_runtime.h>
#include <cuda_fp16.h>
#include <math.h>
#include <stdint.h>

// Problem constants
#define NB        8
#define CD        64
#define HH        4096
#define NPTS      (NB*HH)    // 32768
#define NCODE     8192
#define ZQ_ELEMS  (NB*CD*HH) // 2097152

// Output layout (flat float32): [z_q | loss | indices | perplexity]
#define OUT_ZQ    0
#define OUT_LOSS  ZQ_ELEMS
#define OUT_IDX   (ZQ_ELEMS + 1)
#define OUT_PERP  (ZQ_ELEMS + 1 + NPTS)

#define LO_SCALE   4096.0f
#define LO_INV     2.44140625e-4f   // 1/4096

// B fragments for mma.m16n8k16.f16: [nf(1024)][kc(4)][lane(32)] uint4 =
// (b0_hi, b1_hi, b0_lo, b1_lo); b0 = half2{B[k0][c],B[k0+1][c]}, b1 = k0+8 pair,
// c = nf*8 + lane/4, k0 = kc*16 + (lane%4)*2.  B[k][n] = 2*E[n][k], hi/lo fp16
// split with lo scaled by 4096.
__device__ uint4  g_Bfrag[1024 * 4 * 32];   // 2 MB
__device__ float  g_enorm[NCODE];
__device__ int    g_idx[NPTS];
__device__ int    g_hist[NCODE];
__device__ float  g_partial[2048];

// ---------------------------------------------------------------------------
__device__ __forceinline__ uint32_t pack_h2(__half a, __half b) {
    __half2 h = __halves2half2(a, b);
    return *(uint32_t*)&h;
}

__device__ __forceinline__ void split16(float f, __half& hi, __half& lo) {
    hi = __float2half_rn(f);
    lo = __float2half_rn((f - __half2float(hi)) * LO_SCALE);
}

__device__ __forceinline__ void mma_f16(float& d0, float& d1, float& d2, float& d3,
                                        uint32_t a0, uint32_t a1, uint32_t a2, uint32_t a3,
                                        uint32_t b0, uint32_t b1) {
    asm volatile(
        "mma.sync.aligned.m16n8k16.row.col.f32.f16.f16.f32 "
        "{%0,%1,%2,%3},{%4,%5,%6,%7},{%8,%9},{%0,%1,%2,%3};"
        : "+f"(d0), "+f"(d1), "+f"(d2), "+f"(d3)
        : "r"(a0), "r"(a1), "r"(a2), "r"(a3), "r"(b0), "r"(b1));
}

__device__ __forceinline__ void cp_async16(uint32_t saddr, const void* gptr) {
    asm volatile("cp.async.cg.shared.global [%0], [%1], 16;" :: "r"(saddr), "l"(gptr));
}

// ---------------------------------------------------------------------------
// Prep A: |e|^2 (reference rounding chain) + zero histogram
// ---------------------------------------------------------------------------
__global__ void vq_prep(const float* __restrict__ E) {
    int idx = blockIdx.x * 256 + threadIdx.x;
    if (idx < NCODE) {
        const float* r = E + idx * CD;
        float s = 0.f;
#pragma unroll
        for (int d = 0; d < CD; d++) s = __fadd_rn(s, __fmul_rn(r[d], r[d]));
        g_enorm[idx] = s;
        g_hist[idx] = 0;
    }
}

// ---------------------------------------------------------------------------
// Prep B: pack codebook into m16n8k16 fragment-lane order, fp16 hi/lo of 2E.
// grid 512 x 256 -> 131072 threads, one uint4 each.
// ---------------------------------------------------------------------------
__global__ void vq_prep_bfrag(const float* __restrict__ E) {
    int idx = blockIdx.x * 256 + threadIdx.x;     // [nf*4+kc]*32 + lane
    int lane = idx & 31;
    int kc = (idx >> 5) & 3;
    int nf = idx >> 7;
    int n = nf * 8 + (lane >> 2);
    int k0 = kc * 16 + (lane & 3) * 2;
    const float* r = E + n * CD;
    float f0 = 2.0f * r[k0];
    float f1 = 2.0f * r[k0 + 1];
    float f2 = 2.0f * r[k0 + 8];
    float f3 = 2.0f * r[k0 + 9];
    __half h0, l0, h1, l1, h2, l2, h3, l3;
    split16(f0, h0, l0); split16(f1, h1, l1);
    split16(f2, h2, l2); split16(f3, h3, l3);
    uint4 v;
    v.x = pack_h2(h0, h1);   // b0 hi
    v.y = pack_h2(h2, h3);   // b1 hi
    v.z = pack_h2(l0, l1);   // b0 lo
    v.w = pack_h2(l2, l3);   // b1 lo
    g_Bfrag[idx] = v;
}

// ---------------------------------------------------------------------------
// Fused split-fp16 distance-GEMM + argmax.
// CTA: 256 threads = 8 warps; warp w owns rows [blk*256 + w*32, +32).
// Warp tile m32 x n32, K=64 resident in registers (A hi+lo fp16 pairs).
// dot = Dh + Dx/4096;  v = fl(fl(-zn - en) + dot); first-index argmax.
// grid 128.
// ---------------------------------------------------------------------------
__global__ void __launch_bounds__(256, 1) vq_argmax(const float* __restrict__ z) {
    __shared__ uint4 Bs[2][512];     // 16 KB double buffer (n-tile of 32 codes)

    const int tid = threadIdx.x;
    const int lane = tid & 31;
    const int w = tid >> 5;
    const int blk = blockIdx.x;
    const int b = (blk * 256) >> 12;
    const int hb = (blk * 256) & (HH - 1);
    const float* zb = z + b * (CD * HH);
    const int hw = hb + w * 32;

    // ---- -|z|^2 per row (reference sequential chain); lane l -> row hw+l
    float s = 0.f;
    {
        int h = hw + lane;
#pragma unroll
        for (int k = 0; k < CD; k++) {
            float v = zb[k * HH + h];
            s = __fadd_rn(s, __fmul_rn(v, v));
        }
    }
    float nznl = -s;
    float nzn[2][2];
#pragma unroll
    for (int mf = 0; mf < 2; mf++) {
        nzn[mf][0] = __shfl_sync(0xffffffffu, nznl, mf * 16 + (lane >> 2));
        nzn[mf][1] = __shfl_sync(0xffffffffu, nznl, mf * 16 + (lane >> 2) + 8);
    }

    // ---- A fragments (hi/lo fp16), resident for whole N sweep.
    // a0:{r,k0,k0+1} a1:{r+8,..} a2:{r,k0+8,k0+9} a3:{r+8,k0+8,k0+9}
    uint32_t Ahi[2][4][4], Alo[2][4][4];
#pragma unroll
    for (int mf = 0; mf < 2; mf++) {
        int r0 = hw + mf * 16 + (lane >> 2);
        int r1 = r0 + 8;
#pragma unroll
        for (int kc = 0; kc < 4; kc++) {
            int k0 = kc * 16 + (lane & 3) * 2;
#pragma unroll
            for (int q = 0; q < 4; q++) {
                int rr = (q & 1) ? r1 : r0;
                int kk = k0 + ((q & 2) ? 8 : 0);
                float fA = zb[kk * HH + rr];
                float fB = zb[(kk + 1) * HH + rr];
                __half hA, lA, hB, lB;
                split16(fA, hA, lA);
                split16(fB, hB, lB);
                Ahi[mf][kc][q] = pack_h2(hA, hB);
                Alo[mf][kc][q] = pack_h2(lA, lB);
            }
        }
    }

    float best[2][2];
    int   bidx[2][2];
#pragma unroll
    for (int mf = 0; mf < 2; mf++)
#pragma unroll
        for (int rr = 0; rr < 2; rr++) { best[mf][rr] = -3.4e38f; bidx[mf][rr] = 0; }

    const int NT = NCODE / 32;   // 256 n-tiles

    // prologue: stage tile 0 into buf 0 (512 uint4, 2 per thread)
    {
#pragma unroll
        for (int i = 0; i < 2; i++) {
            int q = tid + i * 256;
            uint32_t sa = (uint32_t)__cvta_generic_to_shared(&Bs[0][q]);
            cp_async16(sa, &g_Bfrag[q]);
        }
        asm volatile("cp.async.commit_group;" ::: "memory");
    }

#pragma unroll 1
    for (int t = 0; t < NT; t++) {
        const int cur = t & 1;
        if (t + 1 < NT) {
            const int nxt = cur ^ 1;
#pragma unroll
            for (int i = 0; i < 2; i++) {
                int q = tid + i * 256;
                uint32_t sa = (uint32_t)__cvta_generic_to_shared(&Bs[nxt][q]);
                cp_async16(sa, &g_Bfrag[(t + 1) * 512 + q]);
            }
            asm volatile("cp.async.commit_group;" ::: "memory");
            asm volatile("cp.async.wait_group 1;" ::: "memory");
        } else {
            asm volatile("cp.async.wait_group 0;" ::: "memory");
        }
        __syncthreads();   // tile t visible

        float Dh[2][4][4], Dx[2][4][4];
#pragma unroll
        for (int mf = 0; mf < 2; mf++)
#pragma unroll
            for (int nf = 0; nf < 4; nf++)
#pragma unroll
                for (int c = 0; c < 4; c++) { Dh[mf][nf][c] = 0.f; Dx[mf][nf][c] = 0.f; }

#pragma unroll
        for (int kc = 0; kc < 4; kc++) {
            uint4 bq[4];
#pragma unroll
            for (int nf = 0; nf < 4; nf++)
                bq[nf] = Bs[cur][(nf * 4 + kc) * 32 + lane];
#pragma unroll
            for (int mf = 0; mf < 2; mf++)
#pragma unroll
                for (int nf = 0; nf < 4; nf++) {
                    // hi*hi -> Dh
                    mma_f16(Dh[mf][nf][0], Dh[mf][nf][1], Dh[mf][nf][2], Dh[mf][nf][3],
                            Ahi[mf][kc][0], Ahi[mf][kc][1], Ahi[mf][kc][2], Ahi[mf][kc][3],
                            bq[nf].x, bq[nf].y);
                    // hi*lo + lo*hi -> Dx (scale 4096)
                    mma_f16(Dx[mf][nf][0], Dx[mf][nf][1], Dx[mf][nf][2], Dx[mf][nf][3],
                            Ahi[mf][kc][0], Ahi[mf][kc][1], Ahi[mf][kc][2], Ahi[mf][kc][3],
                            bq[nf].z, bq[nf].w);
                    mma_f16(Dx[mf][nf][0], Dx[mf][nf][1], Dx[mf][nf][2], Dx[mf][nf][3],
                            Alo[mf][kc][0], Alo[mf][kc][1], Alo[mf][kc][2], Alo[mf][kc][3],
                            bq[nf].x, bq[nf].y);
                }
        }
        __syncthreads();   // all reads of buf `cur` done before t+1 overwrites

        // epilogue: dot = Dh + Dx/4096; v = fl(fl(-zn - en) + dot)
        const int nbase = t * 32;
#pragma unroll
        for (int nf = 0; nf < 4; nf++) {
            const int ncol = nbase + nf * 8 + (lane & 3) * 2;
            float2 en2 = *(const float2*)(g_enorm + ncol);
#pragma unroll
            for (int mf = 0; mf < 2; mf++) {
                float dot0 = __fmaf_rn(Dx[mf][nf][0], LO_INV, Dh[mf][nf][0]);
                float dot1 = __fmaf_rn(Dx[mf][nf][1], LO_INV, Dh[mf][nf][1]);
                float dot2 = __fmaf_rn(Dx[mf][nf][2], LO_INV, Dh[mf][nf][2]);
                float dot3 = __fmaf_rn(Dx[mf][nf][3], LO_INV, Dh[mf][nf][3]);
                float v0 = __fadd_rn(__fadd_rn(nzn[mf][0], -en2.x), dot0);
                if (v0 > best[mf][0]) { best[mf][0] = v0; bidx[mf][0] = ncol; }
                float v1 = __fadd_rn(__fadd_rn(nzn[mf][0], -en2.y), dot1);
                if (v1 > best[mf][0]) { best[mf][0] = v1; bidx[mf][0] = ncol + 1; }
                float v2 = __fadd_rn(__fadd_rn(nzn[mf][1], -en2.x), dot2);
                if (v2 > best[mf][1]) { best[mf][1] = v2; bidx[mf][1] = ncol; }
                float v3 = __fadd_rn(__fadd_rn(nzn[mf][1], -en2.y), dot3);
                if (v3 > best[mf][1]) { best[mf][1] = v3; bidx[mf][1] = ncol + 1; }
            }
        }
    }

    // quad reduce (lanes sharing a row differ in lane%4), first-index tie-break
    const int Wrow = blk * 256 + w * 32;
#pragma unroll
    for (int mf = 0; mf < 2; mf++)
#pragma unroll
        for (int rr = 0; rr < 2; rr++) {
            float v = best[mf][rr];
            int ix = bidx[mf][rr];
#pragma unroll
            for (int off = 1; off <= 2; off <<= 1) {
                float ov = __shfl_xor_sync(0xffffffffu, v, off);
                int   oi = __shfl_xor_sync(0xffffffffu, ix, off);
                if (ov > v || (ov == v && oi < ix)) { v = ov; ix = oi; }
            }
            if ((lane & 3) == 0)
                g_idx[Wrow + mf * 16 + (lane >> 2) + rr * 8] = ix;
        }
}

// ---------------------------------------------------------------------------
// Gather z_q into out, accumulate per-block SSD partial.
// ---------------------------------------------------------------------------
__global__ void vq_gather(const float* __restrict__ z, const float* __restrict__ E,
                          float* __restrict__ out) {
    __shared__ float red[256];
    int tid = threadIdx.x;
    int base = (blockIdx.x * 256 + tid) * 4;
    int h = base & (HH - 1);
    int c = (base >> 12) & (CD - 1);
    int b = base >> 18;
    const int* gi = g_idx + b * HH + h;
    float4 zv = *(const float4*)(z + base);
    float e0 = E[gi[0] * CD + c];
    float e1 = E[gi[1] * CD + c];
    float e2 = E[gi[2] * CD + c];
    float e3 = E[gi[3] * CD + c];
    *(float4*)(out + OUT_ZQ + base) = make_float4(e0, e1, e2, e3);
    float d0 = e0 - zv.x, d1 = e1 - zv.y, d2 = e2 - zv.z, d3 = e3 - zv.w;
    red[tid] = d0 * d0 + d1 * d1 + d2 * d2 + d3 * d3;
    __syncthreads();
    for (int off = 128; off > 0; off >>= 1) {
        if (tid < off) red[tid] += red[tid + off];
        __syncthreads();
    }
    if (tid == 0) g_partial[blockIdx.x] = red[0];
}

// ---------------------------------------------------------------------------
__global__ void vq_hist(float* __restrict__ out) {
    int n = blockIdx.x * 256 + threadIdx.x;
    int idx = g_idx[n];
    atomicAdd(&g_hist[idx], 1);
    out[OUT_IDX + n] = (float)idx;
}

// ---------------------------------------------------------------------------
__global__ void vq_final(float* __restrict__ out) {
    __shared__ float red[256];
    int tid = threadIdx.x;

    float s = 0.f;
    for (int i = tid; i < 2048; i += 256) s += g_partial[i];
    red[tid] = s;
    __syncthreads();
    for (int off = 128; off > 0; off >>= 1) {
        if (tid < off) red[tid] += red[tid + off];
        __syncthreads();
    }
    if (tid == 0)
        out[OUT_LOSS] = 1.25f * red[0] / (float)ZQ_ELEMS;
    __syncthreads();

    float ent = 0.f;
    for (int i = tid; i < NCODE; i += 256) {
        float p = (float)g_hist[i] * (1.f / (float)NPTS);
        ent += p * logf(p + 1e-10f);
    }
    red[tid] = ent;
    __syncthreads();
    for (int off = 128; off > 0; off >>= 1) {
        if (tid < off) red[tid] += red[tid + off];
        __syncthreads();
    }
    if (tid == 0) out[OUT_PERP] = expf(-red[0]);
}

// ---------------------------------------------------------------------------
extern "C" void kernel_launch(void* const* d_in, const int* in_sizes, int n_in,
                              void* d_out, int out_size) {
    const float* z = (const float*)d_in[0];        // (8, 64, 4096) f32
    const float* E = (const float*)d_in[1];        // (8192, 64) f32
    float* out = (float*)d_out;

    vq_prep      <<<32, 256>>>(E);
    vq_prep_bfrag<<<512, 256>>>(E);
    vq_argmax    <<<128, 256>>>(z);
    vq_gather    <<<2048, 256>>>(z, E, out);
    vq_hist      <<<NPTS / 256, 256>>>(out);
    vq_final     <<<1, 256>>>(out);
}